// round 1
// baseline (speedup 1.0000x reference)
#include <cuda_runtime.h>

#define B_ 2
#define N_ 256
#define D_ 128
#define NBI 512                       // B*N blocks (b,i)
#define ROWS_TOTAL (NBI * N_)         // 131072 rows of structure_matrix

// ---------------- device scratch (static allocation: allowed) ----------------
__device__ float g_T[ROWS_TOTAL * D_];   // T = S @ A      (64 MB)
__device__ float g_U[ROWS_TOTAL * D_];   // U = S @ C      (64 MB)
__device__ float g_A[D_ * D_];           // Wk Wq^T / sqrt(D)
__device__ float g_C[D_ * D_];           // Wv Wo
__device__ float g_u[D_];                // Wk bq / sqrt(D)
__device__ float g_w[D_];                // Wq bk / sqrt(D)
__device__ float g_e[D_];                // bv Wo
__device__ float g_c0;                   // bk.bq / sqrt(D)
__device__ float g_rj[ROWS_TOTAL];       // S_row . u  + c0   (j-side score bias)
__device__ float g_ck[ROWS_TOTAL];       // S_row . w         (kk-side score bias)

// =======================================================================
// Kernel 0: fold weights.  grid=128 (row a), block=128 (col)
// =======================================================================
__global__ void __launch_bounds__(128) k_pre(
    const float* __restrict__ Wq, const float* __restrict__ bq,
    const float* __restrict__ Wk, const float* __restrict__ bk,
    const float* __restrict__ Wv, const float* __restrict__ bv,
    const float* __restrict__ Wo, const float* __restrict__ bo)
{
    extern __shared__ float sWq[];              // [128][129]
    const float ISD = 0.08838834764831845f;     // 1/sqrt(128)
    const int tid = threadIdx.x;
    const int a = blockIdx.x;

    for (int idx = tid; idx < D_ * D_; idx += 128) {
        int r = idx >> 7, c = idx & 127;
        sWq[r * 129 + c] = Wq[idx];
    }
    __syncthreads();

    // A[a][tid] = sum_d Wk[a][d] * Wq[tid][d] / sqrt(D)
    // C[a][tid] = sum_d Wv[a][d] * Wo[d][tid]
    float accA = 0.f, accC = 0.f;
    #pragma unroll 4
    for (int d = 0; d < D_; d++) {
        accA += __ldg(&Wk[a * D_ + d]) * sWq[tid * 129 + d];
        accC += __ldg(&Wv[a * D_ + d]) * __ldg(&Wo[d * D_ + tid]);
    }
    g_A[a * D_ + tid] = accA * ISD;
    g_C[a * D_ + tid] = accC;

    if (a == 0) {
        float su = 0.f, sw = 0.f, se = 0.f;
        for (int d = 0; d < D_; d++) {
            su += __ldg(&Wk[tid * D_ + d]) * __ldg(&bq[d]);
            sw += sWq[tid * 129 + d] * __ldg(&bk[d]);
            se += __ldg(&bv[d]) * __ldg(&Wo[d * D_ + tid]);
        }
        g_u[tid] = su * ISD;
        g_w[tid] = sw * ISD;
        g_e[tid] = se;
        if (tid == 0) {
            float c = 0.f;
            for (int d = 0; d < D_; d++) c += bk[d] * bq[d];
            g_c0 = c * ISD;
        }
    }
    (void)bo;
}

// =======================================================================
// Kernel 1: T|U = S @ [A|C], plus rj/ck bias dots.
// grid = 1024 blocks x 128 rows, block = 256 threads.
// SMEM: sS [128][129], sW [128][256]  (= 197,120 B)
// =======================================================================
#define K1_ROWS 128
#define K1_SP 129
#define K1_SMEM_F (K1_ROWS * K1_SP + D_ * 256)

__global__ void __launch_bounds__(256) k_proj(const float* __restrict__ S)
{
    extern __shared__ float sm1[];
    float* sS = sm1;                      // [128][129]
    float* sW = sm1 + K1_ROWS * K1_SP;    // [128][256]  cols 0-127 = A, 128-255 = C

    const int tid = threadIdx.x;
    const long r0 = (long)blockIdx.x * K1_ROWS;
    const float* Sp = S + r0 * D_;

    for (int idx = tid; idx < K1_ROWS * D_; idx += 256) {
        int r = idx >> 7, k = idx & 127;
        sS[r * K1_SP + k] = Sp[idx];
    }
    for (int idx = tid; idx < D_ * D_; idx += 256) {
        int k = idx >> 7, c = idx & 127;
        sW[k * 256 + c]       = g_A[idx];
        sW[k * 256 + 128 + c] = g_C[idx];
    }
    __syncthreads();

    const int ty = tid >> 4;   // rows ty*8 .. +8
    const int tx = tid & 15;   // cols tx*16 .. +16

    float acc[8][16];
    #pragma unroll
    for (int i = 0; i < 8; i++)
        #pragma unroll
        for (int j = 0; j < 16; j++) acc[i][j] = 0.f;

    #pragma unroll 4
    for (int k = 0; k < D_; k++) {
        float av[8];
        #pragma unroll
        for (int i = 0; i < 8; i++) av[i] = sS[(ty * 8 + i) * K1_SP + k];
        float bv[16];
        #pragma unroll
        for (int j4 = 0; j4 < 4; j4++) {
            float4 b4 = *reinterpret_cast<const float4*>(&sW[k * 256 + tx * 16 + j4 * 4]);
            bv[j4 * 4 + 0] = b4.x; bv[j4 * 4 + 1] = b4.y;
            bv[j4 * 4 + 2] = b4.z; bv[j4 * 4 + 3] = b4.w;
        }
        #pragma unroll
        for (int i = 0; i < 8; i++)
            #pragma unroll
            for (int j = 0; j < 16; j++)
                acc[i][j] += av[i] * bv[j];
    }

    float* dst = (tx < 8) ? g_T : g_U;
    const int cbase = (tx & 7) * 16;
    #pragma unroll
    for (int i = 0; i < 8; i++) {
        long r = r0 + ty * 8 + i;
        #pragma unroll
        for (int j4 = 0; j4 < 4; j4++) {
            float4 v = make_float4(acc[i][j4 * 4 + 0], acc[i][j4 * 4 + 1],
                                   acc[i][j4 * 4 + 2], acc[i][j4 * 4 + 3]);
            *reinterpret_cast<float4*>(&dst[r * D_ + cbase + j4 * 4]) = v;
        }
    }

    // rj / ck (sS unchanged, no extra sync needed)
    if (tid < 128) {
        const int r = tid;
        float s = 0.f;
        #pragma unroll 4
        for (int k = 0; k < D_; k++) s += sS[r * K1_SP + k] * g_u[k];
        g_rj[r0 + r] = s + g_c0;
    } else {
        const int r = tid - 128;
        float s = 0.f;
        #pragma unroll 4
        for (int k = 0; k < D_; k++) s += sS[r * K1_SP + k] * g_w[k];
        g_ck[r0 + r] = s;
    }
}

// =======================================================================
// Kernel 2: per (b,i): P = relu(T S^T + rj + ck); out = P U + rowsum*e + bo;
//           x = out + S; LayerNorm(x).
// grid = 512, block = 512 threads.
// =======================================================================
#define TBK 32
#define SPT 130
#define SPS 129
#define SPU 132
#define SPP 33
#define K2_SMEM_F (256 * SPT + TBK * SPS + TBK * SPU + 256 * SPP + 5 * 256)

__global__ void __launch_bounds__(512) k_attn(
    const float* __restrict__ S,
    const float* __restrict__ bo,
    const float* __restrict__ ln_g,
    const float* __restrict__ ln_b,
    float* __restrict__ out)
{
    extern __shared__ float sm2[];
    float* sT    = sm2;                    // [256][130] (later reused for x)
    float* sS    = sT + 256 * SPT;         // [32][129]
    float* sU    = sS + TBK * SPS;         // [32][132]
    float* sP    = sU + TBK * SPU;         // [256][33]
    float* srj   = sP + 256 * SPP;
    float* sck   = srj + 256;
    float* sRow  = sck + 256;
    float* sMu   = sRow + 256;
    float* sRstd = sMu + 256;

    const int tid = threadIdx.x;
    const int bi = blockIdx.x;
    const long base = (long)bi * (N_ * D_);

    // stage T_i
    const float* Tp = g_T + base;
    for (int idx = tid; idx < N_ * D_; idx += 512) {
        int j = idx >> 7, k = idx & 127;
        sT[j * SPT + k] = Tp[idx];
    }
    if (tid < 256) {
        srj[tid]  = g_rj[bi * N_ + tid];
        sck[tid]  = g_ck[bi * N_ + tid];
        sRow[tid] = 0.f;
    }

    float acc[8][8];
    #pragma unroll
    for (int a = 0; a < 8; a++)
        #pragma unroll
        for (int b = 0; b < 8; b++) acc[a][b] = 0.f;

    const int pj = tid >> 3, pk = tid & 7;    // stage-2b mapping (4x4 of P)
    const int tj = tid >> 4, td = tid & 15;   // stage-2c mapping (8x8 of out)

    const float* Sp = S + base;
    const float* Up = g_U + base;

    for (int t = 0; t < N_ / TBK; t++) {
        const int kk0 = t * TBK;
        __syncthreads();   // prev tile's sP/sU consumers done; sT staged (t==0)
        for (int idx = tid; idx < TBK * D_; idx += 512) {
            int r = idx >> 7, k = idx & 127;
            sS[r * SPS + k] = Sp[(long)(kk0 + r) * D_ + k];
            sU[r * SPU + k] = Up[(long)(kk0 + r) * D_ + k];
        }
        __syncthreads();

        // ---- P tile: relu(T . S^T + rj + ck) ----
        {
            float p[4][4];
            #pragma unroll
            for (int a = 0; a < 4; a++)
                #pragma unroll
                for (int c = 0; c < 4; c++) p[a][c] = 0.f;

            #pragma unroll 4
            for (int k = 0; k < D_; k++) {
                float av[4], bv[4];
                #pragma unroll
                for (int a = 0; a < 4; a++) av[a] = sT[(pj * 4 + a) * SPT + k];
                #pragma unroll
                for (int c = 0; c < 4; c++) bv[c] = sS[(pk * 4 + c) * SPS + k];
                #pragma unroll
                for (int a = 0; a < 4; a++)
                    #pragma unroll
                    for (int c = 0; c < 4; c++) p[a][c] += av[a] * bv[c];
            }
            #pragma unroll
            for (int a = 0; a < 4; a++) {
                const float rj_v = srj[pj * 4 + a];
                #pragma unroll
                for (int c = 0; c < 4; c++) {
                    float sc = p[a][c] + rj_v + sck[kk0 + pk * 4 + c];
                    sP[(pj * 4 + a) * SPP + pk * 4 + c] = fmaxf(sc, 0.f);
                }
            }
        }
        __syncthreads();

        // ---- rowsum of P tile ----
        if (tid < 256) {
            float s = 0.f;
            #pragma unroll
            for (int kk = 0; kk < TBK; kk++) s += sP[tid * SPP + kk];
            sRow[tid] += s;
        }

        // ---- out += P @ U ----
        #pragma unroll 2
        for (int kk = 0; kk < TBK; kk++) {
            float pv[8], uv[8];
            #pragma unroll
            for (int a = 0; a < 8; a++) pv[a] = sP[(tj * 8 + a) * SPP + kk];
            float4 u0 = *reinterpret_cast<const float4*>(&sU[kk * SPU + td * 8]);
            float4 u1 = *reinterpret_cast<const float4*>(&sU[kk * SPU + td * 8 + 4]);
            uv[0] = u0.x; uv[1] = u0.y; uv[2] = u0.z; uv[3] = u0.w;
            uv[4] = u1.x; uv[5] = u1.y; uv[6] = u1.z; uv[7] = u1.w;
            #pragma unroll
            for (int a = 0; a < 8; a++)
                #pragma unroll
                for (int b = 0; b < 8; b++) acc[a][b] += pv[a] * uv[b];
        }
    }
    __syncthreads();   // rowsum complete, everyone done with sT/sP

    // ---- epilogue: x = out + rowsum*e + bo + S  (store into sT buffer) ----
    #pragma unroll
    for (int a = 0; a < 8; a++) {
        const int j = tj * 8 + a;
        const float rs = sRow[j];
        #pragma unroll
        for (int b4 = 0; b4 < 2; b4++) {
            const int d0 = td * 8 + b4 * 4;
            float4 sv  = __ldg(reinterpret_cast<const float4*>(&S[base + (long)j * D_ + d0]));
            float4 ev  = *reinterpret_cast<const float4*>(&g_e[d0]);
            float4 bov = __ldg(reinterpret_cast<const float4*>(&bo[d0]));
            sT[j * SPT + d0 + 0] = acc[a][b4 * 4 + 0] + rs * ev.x + bov.x + sv.x;
            sT[j * SPT + d0 + 1] = acc[a][b4 * 4 + 1] + rs * ev.y + bov.y + sv.y;
            sT[j * SPT + d0 + 2] = acc[a][b4 * 4 + 2] + rs * ev.z + bov.z + sv.z;
            sT[j * SPT + d0 + 3] = acc[a][b4 * 4 + 3] + rs * ev.w + bov.w + sv.w;
        }
    }
    __syncthreads();

    // ---- LayerNorm stats per row ----
    if (tid < 256) {
        const int j = tid;
        float s = 0.f, s2 = 0.f;
        #pragma unroll 4
        for (int d = 0; d < D_; d++) {
            float v = sT[j * SPT + d];
            s += v; s2 += v * v;
        }
        float mu  = s * (1.f / 128.f);
        float var = s2 * (1.f / 128.f) - mu * mu;
        sMu[j]   = mu;
        sRstd[j] = rsqrtf(var + 1e-5f);
    }
    __syncthreads();

    // ---- normalized coalesced store ----
    for (int idx = tid; idx < N_ * D_; idx += 512) {
        int j = idx >> 7, d = idx & 127;
        float v = (sT[j * SPT + d] - sMu[j]) * sRstd[j] * __ldg(&ln_g[d]) + __ldg(&ln_b[d]);
        out[base + idx] = v;
    }
}

// =======================================================================
// launch
// =======================================================================
extern "C" void kernel_launch(void* const* d_in, const int* in_sizes, int n_in,
                              void* d_out, int out_size)
{
    (void)in_sizes; (void)n_in; (void)out_size;
    // metadata order: hidden_states, structure_matrix, Wq,bq, Wk,bk, Wv,bv, Wo,bo, ln_g, ln_b
    const float* S    = (const float*)d_in[1];
    const float* Wq   = (const float*)d_in[2];
    const float* bq   = (const float*)d_in[3];
    const float* Wk   = (const float*)d_in[4];
    const float* bk   = (const float*)d_in[5];
    const float* Wv   = (const float*)d_in[6];
    const float* bv   = (const float*)d_in[7];
    const float* Wo   = (const float*)d_in[8];
    const float* bo   = (const float*)d_in[9];
    const float* ln_g = (const float*)d_in[10];
    const float* ln_b = (const float*)d_in[11];
    float* out = (float*)d_out;

    const size_t sm0 = (size_t)(128 * 129) * sizeof(float);   //  66,048 B
    const size_t sm1 = (size_t)K1_SMEM_F * sizeof(float);     // 197,120 B
    const size_t sm2 = (size_t)K2_SMEM_F * sizeof(float);     // 205,440 B
    cudaFuncSetAttribute(k_pre,  cudaFuncAttributeMaxDynamicSharedMemorySize, (int)sm0);
    cudaFuncSetAttribute(k_proj, cudaFuncAttributeMaxDynamicSharedMemorySize, (int)sm1);
    cudaFuncSetAttribute(k_attn, cudaFuncAttributeMaxDynamicSharedMemorySize, (int)sm2);

    k_pre <<<128, 128, sm0>>>(Wq, bq, Wk, bk, Wv, bv, Wo, bo);
    k_proj<<<1024, 256, sm1>>>(S);
    k_attn<<<NBI, 512, sm2>>>(S, bo, ln_g, ln_b, out);
}

// round 2
// speedup vs baseline: 1.0019x; 1.0019x over previous
#include <cuda_runtime.h>

#define B_ 2
#define N_ 256
#define D_ 128
#define NBI 512                       // B*N blocks (b,i)
#define ROWS_TOTAL (NBI * N_)         // 131072 rows of structure_matrix

// ---------------- device scratch (static allocation: allowed) ----------------
__device__ float g_T[ROWS_TOTAL * D_];   // T = S @ A      (64 MB)
__device__ float g_U[ROWS_TOTAL * D_];   // U = S @ C      (64 MB)
__device__ float g_A[D_ * D_];           // Wk Wq^T / sqrt(D)
__device__ float g_C[D_ * D_];           // Wv Wo
__device__ float g_u[D_];                // Wk bq / sqrt(D)
__device__ float g_w[D_];                // Wq bk / sqrt(D)
__device__ float g_e[D_];                // bv Wo
__device__ float g_c0;                   // bk.bq / sqrt(D)
__device__ float g_rj[ROWS_TOTAL];       // S_row . u  + c0   (j-side score bias)
__device__ float g_ck[ROWS_TOTAL];       // S_row . w         (kk-side score bias)

// =======================================================================
// Kernel 0: fold weights.  grid=128 (row a), block=128 (col)
// =======================================================================
__global__ void __launch_bounds__(128) k_pre(
    const float* __restrict__ Wq, const float* __restrict__ bq,
    const float* __restrict__ Wk, const float* __restrict__ bk,
    const float* __restrict__ Wv, const float* __restrict__ bv,
    const float* __restrict__ Wo, const float* __restrict__ bo)
{
    extern __shared__ float sWq[];              // [128][129]
    const float ISD = 0.08838834764831845f;     // 1/sqrt(128)
    const int tid = threadIdx.x;
    const int a = blockIdx.x;

    for (int idx = tid; idx < D_ * D_; idx += 128) {
        int r = idx >> 7, c = idx & 127;
        sWq[r * 129 + c] = Wq[idx];
    }
    __syncthreads();

    // A[a][tid] = sum_d Wk[a][d] * Wq[tid][d] / sqrt(D)
    // C[a][tid] = sum_d Wv[a][d] * Wo[d][tid]
    float accA = 0.f, accC = 0.f;
    #pragma unroll 4
    for (int d = 0; d < D_; d++) {
        accA += __ldg(&Wk[a * D_ + d]) * sWq[tid * 129 + d];
        accC += __ldg(&Wv[a * D_ + d]) * __ldg(&Wo[d * D_ + tid]);
    }
    g_A[a * D_ + tid] = accA * ISD;
    g_C[a * D_ + tid] = accC;

    if (a == 0) {
        float su = 0.f, sw = 0.f, se = 0.f;
        for (int d = 0; d < D_; d++) {
            su += __ldg(&Wk[tid * D_ + d]) * __ldg(&bq[d]);
            sw += sWq[tid * 129 + d] * __ldg(&bk[d]);
            se += __ldg(&bv[d]) * __ldg(&Wo[d * D_ + tid]);
        }
        g_u[tid] = su * ISD;
        g_w[tid] = sw * ISD;
        g_e[tid] = se;
        if (tid == 0) {
            float c = 0.f;
            for (int d = 0; d < D_; d++) c += bk[d] * bq[d];
            g_c0 = c * ISD;
        }
    }
    (void)bo;
}

// =======================================================================
// Kernel 1: T|U = S @ [A|C], plus rj/ck bias dots.
// grid = 1024 blocks x 128 rows, block = 256 threads.
// SMEM: sS [128][129], sW [128][256]  (= 197,120 B)
// =======================================================================
#define K1_ROWS 128
#define K1_SP 129
#define K1_SMEM_F (K1_ROWS * K1_SP + D_ * 256)

__global__ void __launch_bounds__(256) k_proj(const float* __restrict__ S)
{
    extern __shared__ float sm1[];
    float* sS = sm1;                      // [128][129]
    float* sW = sm1 + K1_ROWS * K1_SP;    // [128][256]  cols 0-127 = A, 128-255 = C

    const int tid = threadIdx.x;
    const long r0 = (long)blockIdx.x * K1_ROWS;
    const float* Sp = S + r0 * D_;

    for (int idx = tid; idx < K1_ROWS * D_; idx += 256) {
        int r = idx >> 7, k = idx & 127;
        sS[r * K1_SP + k] = Sp[idx];
    }
    for (int idx = tid; idx < D_ * D_; idx += 256) {
        int k = idx >> 7, c = idx & 127;
        sW[k * 256 + c]       = g_A[idx];
        sW[k * 256 + 128 + c] = g_C[idx];
    }
    __syncthreads();

    const int ty = tid >> 4;   // rows ty*8 .. +8
    const int tx = tid & 15;   // cols tx*16 .. +16

    float acc[8][16];
    #pragma unroll
    for (int i = 0; i < 8; i++)
        #pragma unroll
        for (int j = 0; j < 16; j++) acc[i][j] = 0.f;

    #pragma unroll 4
    for (int k = 0; k < D_; k++) {
        float av[8];
        #pragma unroll
        for (int i = 0; i < 8; i++) av[i] = sS[(ty * 8 + i) * K1_SP + k];
        float bv[16];
        #pragma unroll
        for (int j4 = 0; j4 < 4; j4++) {
            float4 b4 = *reinterpret_cast<const float4*>(&sW[k * 256 + tx * 16 + j4 * 4]);
            bv[j4 * 4 + 0] = b4.x; bv[j4 * 4 + 1] = b4.y;
            bv[j4 * 4 + 2] = b4.z; bv[j4 * 4 + 3] = b4.w;
        }
        #pragma unroll
        for (int i = 0; i < 8; i++)
            #pragma unroll
            for (int j = 0; j < 16; j++)
                acc[i][j] += av[i] * bv[j];
    }

    float* dst = (tx < 8) ? g_T : g_U;
    const int cbase = (tx & 7) * 16;
    #pragma unroll
    for (int i = 0; i < 8; i++) {
        long r = r0 + ty * 8 + i;
        #pragma unroll
        for (int j4 = 0; j4 < 4; j4++) {
            float4 v = make_float4(acc[i][j4 * 4 + 0], acc[i][j4 * 4 + 1],
                                   acc[i][j4 * 4 + 2], acc[i][j4 * 4 + 3]);
            *reinterpret_cast<float4*>(&dst[r * D_ + cbase + j4 * 4]) = v;
        }
    }

    // rj / ck (sS unchanged, no extra sync needed)
    if (tid < 128) {
        const int r = tid;
        float s = 0.f;
        #pragma unroll 4
        for (int k = 0; k < D_; k++) s += sS[r * K1_SP + k] * g_u[k];
        g_rj[r0 + r] = s + g_c0;
    } else {
        const int r = tid - 128;
        float s = 0.f;
        #pragma unroll 4
        for (int k = 0; k < D_; k++) s += sS[r * K1_SP + k] * g_w[k];
        g_ck[r0 + r] = s;
    }
}

// =======================================================================
// Kernel 2: per (b,i): P = relu(T S^T + rj + ck); out = P U + rowsum*e + bo;
//           x = out + S; LayerNorm(x).
// grid = 512, block = 512 threads.
// =======================================================================
#define TBK 32
#define SPT 130
#define SPS 129
#define SPU 132
#define SPP 33
#define K2_SMEM_F (256 * SPT + TBK * SPS + TBK * SPU + 256 * SPP + 5 * 256)

__global__ void __launch_bounds__(512) k_attn(
    const float* __restrict__ S,
    const float* __restrict__ bo,
    const float* __restrict__ ln_g,
    const float* __restrict__ ln_b,
    float* __restrict__ out)
{
    extern __shared__ float sm2[];
    float* sT    = sm2;                    // [256][130] (later reused for x)
    float* sS    = sT + 256 * SPT;         // [32][129]
    float* sU    = sS + TBK * SPS;         // [32][132]
    float* sP    = sU + TBK * SPU;         // [256][33]
    float* srj   = sP + 256 * SPP;
    float* sck   = srj + 256;
    float* sRow  = sck + 256;
    float* sMu   = sRow + 256;
    float* sRstd = sMu + 256;

    const int tid = threadIdx.x;
    const int bi = blockIdx.x;
    const long base = (long)bi * (N_ * D_);

    // stage T_i
    const float* Tp = g_T + base;
    for (int idx = tid; idx < N_ * D_; idx += 512) {
        int j = idx >> 7, k = idx & 127;
        sT[j * SPT + k] = Tp[idx];
    }
    if (tid < 256) {
        srj[tid]  = g_rj[bi * N_ + tid];
        sck[tid]  = g_ck[bi * N_ + tid];
        sRow[tid] = 0.f;
    }

    float acc[8][8];
    #pragma unroll
    for (int a = 0; a < 8; a++)
        #pragma unroll
        for (int b = 0; b < 8; b++) acc[a][b] = 0.f;

    const int pj = tid >> 3, pk = tid & 7;    // stage-2b mapping (4x4 of P)
    const int tj = tid >> 4, td = tid & 15;   // stage-2c mapping (8x8 of out)

    const float* Sp = S + base;
    const float* Up = g_U + base;

    for (int t = 0; t < N_ / TBK; t++) {
        const int kk0 = t * TBK;
        __syncthreads();   // prev tile's sP/sU consumers done; sT staged (t==0)
        for (int idx = tid; idx < TBK * D_; idx += 512) {
            int r = idx >> 7, k = idx & 127;
            sS[r * SPS + k] = Sp[(long)(kk0 + r) * D_ + k];
            sU[r * SPU + k] = Up[(long)(kk0 + r) * D_ + k];
        }
        __syncthreads();

        // ---- P tile: relu(T . S^T + rj + ck) ----
        {
            float p[4][4];
            #pragma unroll
            for (int a = 0; a < 4; a++)
                #pragma unroll
                for (int c = 0; c < 4; c++) p[a][c] = 0.f;

            #pragma unroll 4
            for (int k = 0; k < D_; k++) {
                float av[4], bv[4];
                #pragma unroll
                for (int a = 0; a < 4; a++) av[a] = sT[(pj * 4 + a) * SPT + k];
                #pragma unroll
                for (int c = 0; c < 4; c++) bv[c] = sS[(pk * 4 + c) * SPS + k];
                #pragma unroll
                for (int a = 0; a < 4; a++)
                    #pragma unroll
                    for (int c = 0; c < 4; c++) p[a][c] += av[a] * bv[c];
            }
            #pragma unroll
            for (int a = 0; a < 4; a++) {
                const float rj_v = srj[pj * 4 + a];
                #pragma unroll
                for (int c = 0; c < 4; c++) {
                    float sc = p[a][c] + rj_v + sck[kk0 + pk * 4 + c];
                    sP[(pj * 4 + a) * SPP + pk * 4 + c] = fmaxf(sc, 0.f);
                }
            }
        }
        __syncthreads();

        // ---- rowsum of P tile ----
        if (tid < 256) {
            float s = 0.f;
            #pragma unroll
            for (int kk = 0; kk < TBK; kk++) s += sP[tid * SPP + kk];
            sRow[tid] += s;
        }

        // ---- out += P @ U ----
        #pragma unroll 2
        for (int kk = 0; kk < TBK; kk++) {
            float pv[8], uv[8];
            #pragma unroll
            for (int a = 0; a < 8; a++) pv[a] = sP[(tj * 8 + a) * SPP + kk];
            float4 u0 = *reinterpret_cast<const float4*>(&sU[kk * SPU + td * 8]);
            float4 u1 = *reinterpret_cast<const float4*>(&sU[kk * SPU + td * 8 + 4]);
            uv[0] = u0.x; uv[1] = u0.y; uv[2] = u0.z; uv[3] = u0.w;
            uv[4] = u1.x; uv[5] = u1.y; uv[6] = u1.z; uv[7] = u1.w;
            #pragma unroll
            for (int a = 0; a < 8; a++)
                #pragma unroll
                for (int b = 0; b < 8; b++) acc[a][b] += pv[a] * uv[b];
        }
    }
    __syncthreads();   // rowsum complete, everyone done with sT/sP

    // ---- epilogue: x = out + rowsum*e + bo + S  (store into sT buffer) ----
    #pragma unroll
    for (int a = 0; a < 8; a++) {
        const int j = tj * 8 + a;
        const float rs = sRow[j];
        #pragma unroll
        for (int b4 = 0; b4 < 2; b4++) {
            const int d0 = td * 8 + b4 * 4;
            float4 sv  = __ldg(reinterpret_cast<const float4*>(&S[base + (long)j * D_ + d0]));
            float4 ev  = *reinterpret_cast<const float4*>(&g_e[d0]);
            float4 bov = __ldg(reinterpret_cast<const float4*>(&bo[d0]));
            sT[j * SPT + d0 + 0] = acc[a][b4 * 4 + 0] + rs * ev.x + bov.x + sv.x;
            sT[j * SPT + d0 + 1] = acc[a][b4 * 4 + 1] + rs * ev.y + bov.y + sv.y;
            sT[j * SPT + d0 + 2] = acc[a][b4 * 4 + 2] + rs * ev.z + bov.z + sv.z;
            sT[j * SPT + d0 + 3] = acc[a][b4 * 4 + 3] + rs * ev.w + bov.w + sv.w;
        }
    }
    __syncthreads();

    // ---- LayerNorm stats per row ----
    if (tid < 256) {
        const int j = tid;
        float s = 0.f, s2 = 0.f;
        #pragma unroll 4
        for (int d = 0; d < D_; d++) {
            float v = sT[j * SPT + d];
            s += v; s2 += v * v;
        }
        float mu  = s * (1.f / 128.f);
        float var = s2 * (1.f / 128.f) - mu * mu;
        sMu[j]   = mu;
        sRstd[j] = rsqrtf(var + 1e-5f);
    }
    __syncthreads();

    // ---- normalized coalesced store ----
    for (int idx = tid; idx < N_ * D_; idx += 512) {
        int j = idx >> 7, d = idx & 127;
        float v = (sT[j * SPT + d] - sMu[j]) * sRstd[j] * __ldg(&ln_g[d]) + __ldg(&ln_b[d]);
        out[base + idx] = v;
    }
}

// =======================================================================
// launch
// =======================================================================
extern "C" void kernel_launch(void* const* d_in, const int* in_sizes, int n_in,
                              void* d_out, int out_size)
{
    (void)in_sizes; (void)n_in; (void)out_size;
    // metadata order: hidden_states, structure_matrix, Wq,bq, Wk,bk, Wv,bv, Wo,bo, ln_g, ln_b
    const float* S    = (const float*)d_in[1];
    const float* Wq   = (const float*)d_in[2];
    const float* bq   = (const float*)d_in[3];
    const float* Wk   = (const float*)d_in[4];
    const float* bk   = (const float*)d_in[5];
    const float* Wv   = (const float*)d_in[6];
    const float* bv   = (const float*)d_in[7];
    const float* Wo   = (const float*)d_in[8];
    const float* bo   = (const float*)d_in[9];
    const float* ln_g = (const float*)d_in[10];
    const float* ln_b = (const float*)d_in[11];
    float* out = (float*)d_out;

    const size_t sm0 = (size_t)(128 * 129) * sizeof(float);   //  66,048 B
    const size_t sm1 = (size_t)K1_SMEM_F * sizeof(float);     // 197,120 B
    const size_t sm2 = (size_t)K2_SMEM_F * sizeof(float);     // 205,440 B
    cudaFuncSetAttribute(k_pre,  cudaFuncAttributeMaxDynamicSharedMemorySize, (int)sm0);
    cudaFuncSetAttribute(k_proj, cudaFuncAttributeMaxDynamicSharedMemorySize, (int)sm1);
    cudaFuncSetAttribute(k_attn, cudaFuncAttributeMaxDynamicSharedMemorySize, (int)sm2);

    k_pre <<<128, 128, sm0>>>(Wq, bq, Wk, bk, Wv, bv, Wo, bo);
    k_proj<<<1024, 256, sm1>>>(S);
    k_attn<<<NBI, 512, sm2>>>(S, bo, ln_g, ln_b, out);
}

// round 4
// speedup vs baseline: 1.0910x; 1.0889x over previous
#include <cuda_runtime.h>
#include <stdint.h>

#define B_ 2
#define N_ 256
#define D_ 128
#define NBI 512                       // B*N blocks (b,i)
#define ROWS_TOTAL (NBI * N_)         // 131072 rows of structure_matrix

typedef unsigned long long u64;

// ---------------- device scratch (static allocation: allowed) ----------------
__device__ float g_T[ROWS_TOTAL * D_];   // T = S @ A      (64 MB)
__device__ float g_U[ROWS_TOTAL * D_];   // U = S @ C      (64 MB)
__device__ float g_A[D_ * D_];           // Wk Wq^T / sqrt(D)
__device__ float g_C[D_ * D_];           // Wv Wo
__device__ float g_u[D_];                // Wk bq / sqrt(D)
__device__ float g_w[D_];                // Wq bk / sqrt(D)
__device__ float g_e[D_];                // bv Wo
__device__ float g_c0;                   // bk.bq / sqrt(D)
__device__ float g_rj[ROWS_TOTAL];       // S_row . u  + c0
__device__ float g_ck[ROWS_TOTAL];       // S_row . w

// ---------------- packed f32x2 helpers ----------------
__device__ __forceinline__ void fma2(u64& d, u64 a, u64 b) {
    asm("fma.rn.f32x2 %0, %1, %2, %0;" : "+l"(d) : "l"(a), "l"(b));
}
__device__ __forceinline__ u64 pack2(float lo, float hi) {
    u64 r; asm("mov.b64 %0, {%1, %2};" : "=l"(r) : "f"(lo), "f"(hi)); return r;
}
__device__ __forceinline__ float2 unpack2(u64 v) {
    float2 r; asm("mov.b64 {%0, %1}, %2;" : "=f"(r.x), "=f"(r.y) : "l"(v)); return r;
}

// =======================================================================
// Kernel 0: fold weights.  grid=131, block=128.
//   blocks 0..127 : rows of A and C
//   block  128    : g_u + g_c0      (Wk staged to smem)
//   block  129    : g_w             (Wq staged to smem)
//   block  130    : g_e
// =======================================================================
__global__ void __launch_bounds__(128) k_pre(
    const float* __restrict__ Wq, const float* __restrict__ bq,
    const float* __restrict__ Wk, const float* __restrict__ bk,
    const float* __restrict__ Wv, const float* __restrict__ bv,
    const float* __restrict__ Wo, const float* __restrict__ bo)
{
    extern __shared__ float sWq[];              // [128][129] + 128
    const float ISD = 0.08838834764831845f;     // 1/sqrt(128)
    const int tid = threadIdx.x;
    const int a = blockIdx.x;

    if (a < 128) {
        for (int idx = tid; idx < D_ * D_; idx += 128) {
            int r = idx >> 7, c = idx & 127;
            sWq[r * 129 + c] = Wq[idx];
        }
        __syncthreads();

        float accA = 0.f, accC = 0.f;
        #pragma unroll 16
        for (int d = 0; d < D_; d++) {
            accA += __ldg(&Wk[a * D_ + d]) * sWq[tid * 129 + d];
            accC += __ldg(&Wv[a * D_ + d]) * __ldg(&Wo[d * D_ + tid]);
        }
        g_A[a * D_ + tid] = accA * ISD;
        g_C[a * D_ + tid] = accC;
    } else if (a == 128) {
        // stage Wk (coalesced) then per-thread row dot with bq
        for (int idx = tid; idx < D_ * D_; idx += 128) {
            int r = idx >> 7, c = idx & 127;
            sWq[r * 129 + c] = Wk[idx];
        }
        float* sred = sWq + 128 * 129;
        sred[tid] = bk[tid] * bq[tid];
        __syncthreads();
        float su = 0.f;
        #pragma unroll 16
        for (int d = 0; d < D_; d++) su += sWq[tid * 129 + d] * __ldg(&bq[d]);
        g_u[tid] = su * ISD;
        if (tid == 0) {
            float c = 0.f;
            #pragma unroll 16
            for (int d = 0; d < D_; d++) c += sred[d];
            g_c0 = c * ISD;
        }
    } else if (a == 129) {
        for (int idx = tid; idx < D_ * D_; idx += 128) {
            int r = idx >> 7, c = idx & 127;
            sWq[r * 129 + c] = Wq[idx];
        }
        __syncthreads();
        float sw = 0.f;
        #pragma unroll 16
        for (int d = 0; d < D_; d++) sw += sWq[tid * 129 + d] * __ldg(&bk[d]);
        g_w[tid] = sw * ISD;
    } else {
        float se = 0.f;
        #pragma unroll 16
        for (int d = 0; d < D_; d++) se += __ldg(&bv[d]) * __ldg(&Wo[d * D_ + tid]);
        g_e[tid] = se;
    }
    (void)bo;
}

// =======================================================================
// Kernel 1: T|U = S @ [A|C] with packed FFMA2, plus rj/ck bias dots.
// grid = 1024 blocks x 128 rows, block = 256 threads.
// Thread (ty,tx): rows ty*8..+8, column pairs {2tx+32m : m=0..7}
//   -> 64-bit B loads conflict-free (warp covers words 2tx+.. = all 32 banks)
// SMEM: sS [128][129], sW [128][256]
// =======================================================================
#define K1_ROWS 128
#define K1_SP 129
#define K1_SMEM_F (K1_ROWS * K1_SP + D_ * 256)

__global__ void __launch_bounds__(256) k_proj(const float* __restrict__ S)
{
    extern __shared__ float sm1[];
    float* sS = sm1;                      // [128][129]
    float* sW = sm1 + K1_ROWS * K1_SP;    // [128][256]  cols 0-127 = A, 128-255 = C

    const int tid = threadIdx.x;
    const long r0 = (long)blockIdx.x * K1_ROWS;
    const float* Sp = S + r0 * D_;

    for (int idx = tid; idx < K1_ROWS * D_; idx += 256) {
        int r = idx >> 7, k = idx & 127;
        sS[r * K1_SP + k] = Sp[idx];
    }
    for (int idx = tid; idx < D_ * D_; idx += 256) {
        int k = idx >> 7, c = idx & 127;
        sW[k * 256 + c]       = g_A[idx];
        sW[k * 256 + 128 + c] = g_C[idx];
    }
    __syncthreads();

    const int ty = tid >> 4;   // 0..15 : rows ty*8 .. +8
    const int tx = tid & 15;   // 0..15 : col pairs 2tx + 32m

    u64 acc2[8][8];
    #pragma unroll
    for (int i = 0; i < 8; i++)
        #pragma unroll
        for (int m = 0; m < 8; m++) acc2[i][m] = 0ull;

    #pragma unroll 4
    for (int k = 0; k < D_; k++) {
        u64 av2[8];
        #pragma unroll
        for (int i = 0; i < 8; i++) {
            float v = sS[(ty * 8 + i) * K1_SP + k];
            av2[i] = pack2(v, v);
        }
        u64 bv2[8];
        #pragma unroll
        for (int m = 0; m < 8; m++)
            bv2[m] = *reinterpret_cast<const u64*>(&sW[k * 256 + 2 * tx + 32 * m]);
        #pragma unroll
        for (int i = 0; i < 8; i++)
            #pragma unroll
            for (int m = 0; m < 8; m++)
                fma2(acc2[i][m], av2[i], bv2[m]);
    }

    // store: m=0..3 -> cols 0..127 of A result (g_T); m=4..7 -> g_U
    #pragma unroll
    for (int i = 0; i < 8; i++) {
        long r = r0 + ty * 8 + i;
        #pragma unroll
        for (int m = 0; m < 8; m++) {
            int col = 2 * tx + 32 * m;           // 0..255
            float* dst = (col < 128) ? &g_T[r * D_ + col] : &g_U[r * D_ + (col - 128)];
            float2 v = unpack2(acc2[i][m]);
            *reinterpret_cast<float2*>(dst) = v;
        }
    }

    // rj / ck (sS unchanged, no extra sync needed)
    if (tid < 128) {
        const int r = tid;
        float s = 0.f;
        #pragma unroll 8
        for (int k = 0; k < D_; k++) s += sS[r * K1_SP + k] * g_u[k];
        g_rj[r0 + r] = s + g_c0;
    } else {
        const int r = tid - 128;
        float s = 0.f;
        #pragma unroll 8
        for (int k = 0; k < D_; k++) s += sS[r * K1_SP + k] * g_w[k];
        g_ck[r0 + r] = s;
    }
}

// =======================================================================
// Kernel 2: per (b,i): P = relu(T S^T + rj + ck); out = P U + rowsum*e + bo;
//           x = out + S; LayerNorm(x).   Packed FFMA2 in both GEMMs.
// grid = 512, block = 512 threads.
// =======================================================================
#define TBK 32
#define SPT 130     // even stride -> 8B-aligned 64-bit loads at even k
#define SPS 130
#define SPU 132
#define SPP 33
#define K2_SMEM_F (256 * SPT + TBK * SPS + TBK * SPU + 256 * SPP + 5 * 256)

__global__ void __launch_bounds__(512) k_attn(
    const float* __restrict__ S,
    const float* __restrict__ bo,
    const float* __restrict__ ln_g,
    const float* __restrict__ ln_b,
    float* __restrict__ out)
{
    extern __shared__ float sm2[];
    float* sT    = sm2;                    // [256][130] (later reused for x)
    float* sS    = sT + 256 * SPT;         // [32][130]
    float* sU    = sS + TBK * SPS;         // [32][132]
    float* sP    = sU + TBK * SPU;         // [256][33]
    float* srj   = sP + 256 * SPP;
    float* sck   = srj + 256;
    float* sRow  = sck + 256;
    float* sMu   = sRow + 256;
    float* sRstd = sMu + 256;

    const int tid = threadIdx.x;
    const int bi = blockIdx.x;
    const long base = (long)bi * (N_ * D_);

    // stage T_i
    const float* Tp = g_T + base;
    for (int idx = tid; idx < N_ * D_; idx += 512) {
        int j = idx >> 7, k = idx & 127;
        sT[j * SPT + k] = Tp[idx];
    }
    if (tid < 256) {
        srj[tid]  = g_rj[bi * N_ + tid];
        sck[tid]  = g_ck[bi * N_ + tid];
        sRow[tid] = 0.f;
    }

    u64 acc2[8][4];                        // rows tj*8+a, col pairs 2td+32p
    #pragma unroll
    for (int a = 0; a < 8; a++)
        #pragma unroll
        for (int p = 0; p < 4; p++) acc2[a][p] = 0ull;

    const int pj = tid >> 3, pk = tid & 7;    // GEMM1 mapping (4x4 of P)
    const int tj = tid >> 4, td = tid & 15;   // GEMM2 mapping (8 rows x 8 cols)

    const float* Sp = S + base;
    const float* Up = g_U + base;

    for (int t = 0; t < N_ / TBK; t++) {
        const int kk0 = t * TBK;
        __syncthreads();   // prev tile's sP/sU consumers done; sT staged (t==0)
        for (int idx = tid; idx < TBK * D_; idx += 512) {
            int r = idx >> 7, k = idx & 127;
            sS[r * SPS + k] = Sp[(long)(kk0 + r) * D_ + k];
            sU[r * SPU + k] = Up[(long)(kk0 + r) * D_ + k];
        }
        __syncthreads();

        // ---- P tile: relu(T . S^T + rj + ck), k-paired FFMA2 ----
        {
            u64 p2[4][4];
            #pragma unroll
            for (int a = 0; a < 4; a++)
                #pragma unroll
                for (int c = 0; c < 4; c++) p2[a][c] = 0ull;

            #pragma unroll 8
            for (int k = 0; k < D_; k += 2) {
                u64 av2[4], bv2[4];
                #pragma unroll
                for (int a = 0; a < 4; a++)
                    av2[a] = *reinterpret_cast<const u64*>(&sT[(pj * 4 + a) * SPT + k]);
                #pragma unroll
                for (int c = 0; c < 4; c++)
                    bv2[c] = *reinterpret_cast<const u64*>(&sS[(pk * 4 + c) * SPS + k]);
                #pragma unroll
                for (int a = 0; a < 4; a++)
                    #pragma unroll
                    for (int c = 0; c < 4; c++)
                        fma2(p2[a][c], av2[a], bv2[c]);
            }
            #pragma unroll
            for (int a = 0; a < 4; a++) {
                const float rj_v = srj[pj * 4 + a];
                #pragma unroll
                for (int c = 0; c < 4; c++) {
                    float2 h = unpack2(p2[a][c]);
                    float sc = h.x + h.y + rj_v + sck[kk0 + pk * 4 + c];
                    sP[(pj * 4 + a) * SPP + pk * 4 + c] = fmaxf(sc, 0.f);
                }
            }
        }
        __syncthreads();

        // ---- rowsum of P tile ----
        if (tid < 256) {
            float s = 0.f;
            #pragma unroll
            for (int kk = 0; kk < TBK; kk++) s += sP[tid * SPP + kk];
            sRow[tid] += s;
        }

        // ---- out += P @ U  (col-paired FFMA2, interleaved cols) ----
        #pragma unroll 4
        for (int kk = 0; kk < TBK; kk++) {
            u64 pv2[8], uv2[4];
            #pragma unroll
            for (int a = 0; a < 8; a++) {
                float v = sP[(tj * 8 + a) * SPP + kk];
                pv2[a] = pack2(v, v);
            }
            #pragma unroll
            for (int p = 0; p < 4; p++)
                uv2[p] = *reinterpret_cast<const u64*>(&sU[kk * SPU + 2 * td + 32 * p]);
            #pragma unroll
            for (int a = 0; a < 8; a++)
                #pragma unroll
                for (int p = 0; p < 4; p++)
                    fma2(acc2[a][p], pv2[a], uv2[p]);
        }
    }
    __syncthreads();   // rowsum complete, everyone done with sT/sP

    // ---- epilogue: x = out + rowsum*e + bo + S  (store into sT buffer) ----
    #pragma unroll
    for (int a = 0; a < 8; a++) {
        const int j = tj * 8 + a;
        const float rs = sRow[j];
        #pragma unroll
        for (int p = 0; p < 4; p++) {
            const int d0 = 2 * td + 32 * p;
            float2 v  = unpack2(acc2[a][p]);
            float2 sv = __ldg(reinterpret_cast<const float2*>(&S[base + (long)j * D_ + d0]));
            sT[j * SPT + d0 + 0] = v.x + rs * g_e[d0 + 0] + __ldg(&bo[d0 + 0]) + sv.x;
            sT[j * SPT + d0 + 1] = v.y + rs * g_e[d0 + 1] + __ldg(&bo[d0 + 1]) + sv.y;
        }
    }
    __syncthreads();

    // ---- LayerNorm stats per row ----
    if (tid < 256) {
        const int j = tid;
        float s = 0.f, s2 = 0.f;
        #pragma unroll 8
        for (int d = 0; d < D_; d++) {
            float v = sT[j * SPT + d];
            s += v; s2 += v * v;
        }
        float mu  = s * (1.f / 128.f);
        float var = s2 * (1.f / 128.f) - mu * mu;
        sMu[j]   = mu;
        sRstd[j] = rsqrtf(var + 1e-5f);
    }
    __syncthreads();

    // ---- normalized coalesced store ----
    for (int idx = tid; idx < N_ * D_; idx += 512) {
        int j = idx >> 7, d = idx & 127;
        float v = (sT[j * SPT + d] - sMu[j]) * sRstd[j] * __ldg(&ln_g[d]) + __ldg(&ln_b[d]);
        out[base + idx] = v;
    }
}

// =======================================================================
// launch
// =======================================================================
extern "C" void kernel_launch(void* const* d_in, const int* in_sizes, int n_in,
                              void* d_out, int out_size)
{
    (void)in_sizes; (void)n_in; (void)out_size;
    // metadata order: hidden_states, structure_matrix, Wq,bq, Wk,bk, Wv,bv, Wo,bo, ln_g, ln_b
    const float* S    = (const float*)d_in[1];
    const float* Wq   = (const float*)d_in[2];
    const float* bq   = (const float*)d_in[3];
    const float* Wk   = (const float*)d_in[4];
    const float* bk   = (const float*)d_in[5];
    const float* Wv   = (const float*)d_in[6];
    const float* bv   = (const float*)d_in[7];
    const float* Wo   = (const float*)d_in[8];
    const float* bo   = (const float*)d_in[9];
    const float* ln_g = (const float*)d_in[10];
    const float* ln_b = (const float*)d_in[11];
    float* out = (float*)d_out;

    const size_t sm0 = (size_t)(128 * 129 + 128) * sizeof(float); //  66,560 B
    const size_t sm1 = (size_t)K1_SMEM_F * sizeof(float);         // 197,120 B
    const size_t sm2 = (size_t)K2_SMEM_F * sizeof(float);         // ~205,800 B
    cudaFuncSetAttribute(k_pre,  cudaFuncAttributeMaxDynamicSharedMemorySize, (int)sm0);
    cudaFuncSetAttribute(k_proj, cudaFuncAttributeMaxDynamicSharedMemorySize, (int)sm1);
    cudaFuncSetAttribute(k_attn, cudaFuncAttributeMaxDynamicSharedMemorySize, (int)sm2);

    k_pre <<<131, 128, sm0>>>(Wq, bq, Wk, bk, Wv, bv, Wo, bo);
    k_proj<<<1024, 256, sm1>>>(S);
    k_attn<<<NBI, 512, sm2>>>(S, bo, ln_g, ln_b, out);
}

// round 6
// speedup vs baseline: 1.6836x; 1.5433x over previous
#include <cuda_runtime.h>
#include <cuda_bf16.h>
#include <stdint.h>

#define DI __device__ __forceinline__
typedef uint32_t u32;

#define N_ 256
#define D_ 128
#define NBI 512
#define ROWS_TOTAL (NBI * N_)       // 131072

#define KPW 68                      // u32 words per row in smem operand images (136 bf16)
#define IMG_W (128 * KPW)           // 8704 words = 34816 B per image

// ---------------- global scratch (static: allowed) ----------------
__device__ float g_A[D_ * D_];
__device__ float g_C[D_ * D_];
__device__ __align__(16) float g_u[D_];
__device__ __align__(16) float g_w[D_];
__device__ __align__(16) float g_e[D_];
__device__ float g_c0;
__device__ float g_rj[ROWS_TOTAL], g_ck[ROWS_TOTAL];

__device__ u32 g_Shi[ROWS_TOTAL * 64];   // S split bf16, [row][64 words]
__device__ u32 g_Slo[ROWS_TOTAL * 64];
__device__ u32 g_Thi[ROWS_TOTAL * 64];   // T split bf16
__device__ u32 g_Tlo[ROWS_TOTAL * 64];
__device__ u32 g_Uthi[(size_t)NBI * 128 * 128];  // U^T split bf16, [bi][d][128 words(=256 kk)]
__device__ u32 g_Utlo[(size_t)NBI * 128 * 128];
__device__ u32 g_WAhi[8192], g_WAlo[8192];       // A^T image [n][64 words]
__device__ u32 g_WChi[8192], g_WClo[8192];       // C^T image

// ---------------- helpers ----------------
DI void split2(float v0, float v1, u32& hw, u32& lw) {
    __nv_bfloat16 h0 = __float2bfloat16(v0), h1 = __float2bfloat16(v1);
    float r0 = v0 - __bfloat162float(h0), r1 = v1 - __bfloat162float(h1);
    __nv_bfloat16 l0 = __float2bfloat16(r0), l1 = __float2bfloat16(r1);
    hw = (u32)__bfloat16_as_ushort(h0) | ((u32)__bfloat16_as_ushort(h1) << 16);
    lw = (u32)__bfloat16_as_ushort(l0) | ((u32)__bfloat16_as_ushort(l1) << 16);
}
DI void split1(float v, __nv_bfloat16& h, __nv_bfloat16& l) {
    h = __float2bfloat16(v);
    l = __float2bfloat16(v - __bfloat162float(h));
}

DI void mma_bf16(float* c, u32 a0, u32 a1, u32 a2, u32 a3, u32 b0, u32 b1) {
    asm volatile(
        "mma.sync.aligned.m16n8k16.row.col.f32.bf16.bf16.f32 "
        "{%0,%1,%2,%3}, {%4,%5,%6,%7}, {%8,%9}, {%0,%1,%2,%3};"
        : "+f"(c[0]), "+f"(c[1]), "+f"(c[2]), "+f"(c[3])
        : "r"(a0), "r"(a1), "r"(a2), "r"(a3), "r"(b0), "r"(b1));
}

// one K=128 product into warp tile 32(m) x 64(n); images [row][KPW words]
DI void mma_k128(float acc[2][8][4], const u32* __restrict__ A, const u32* __restrict__ B,
                 int m0, int n0, int g, int t) {
    #pragma unroll
    for (int ks = 0; ks < 8; ks++) {
        const int kw = ks * 8 + t;
        u32 a[2][4], b[8][2];
        #pragma unroll
        for (int mf = 0; mf < 2; mf++) {
            const int r = m0 + mf * 16 + g;
            a[mf][0] = A[r * KPW + kw];
            a[mf][1] = A[(r + 8) * KPW + kw];
            a[mf][2] = A[r * KPW + kw + 4];
            a[mf][3] = A[(r + 8) * KPW + kw + 4];
        }
        #pragma unroll
        for (int nf = 0; nf < 8; nf++) {
            const int nr = n0 + nf * 8 + g;
            b[nf][0] = B[nr * KPW + kw];
            b[nf][1] = B[nr * KPW + kw + 4];
        }
        #pragma unroll
        for (int mf = 0; mf < 2; mf++)
            #pragma unroll
            for (int nf = 0; nf < 8; nf++)
                mma_bf16(acc[mf][nf], a[mf][0], a[mf][1], a[mf][2], a[mf][3],
                         b[nf][0], b[nf][1]);
    }
}
// 3-product split GEMM: hi*hi + hi*lo + lo*hi
DI void gemm3p(float acc[2][8][4], const u32* AH, const u32* AL, const u32* BH, const u32* BL,
               int m0, int n0, int g, int t) {
    mma_k128(acc, AH, BH, m0, n0, g, t);
    mma_k128(acc, AH, BL, m0, n0, g, t);
    mma_k128(acc, AL, BH, m0, n0, g, t);
}

// =======================================================================
// k_pre: fold weights (fp32, proven)
// =======================================================================
__global__ void __launch_bounds__(128) k_pre(
    const float* __restrict__ Wq, const float* __restrict__ bq,
    const float* __restrict__ Wk, const float* __restrict__ bk,
    const float* __restrict__ Wv, const float* __restrict__ bv,
    const float* __restrict__ Wo)
{
    extern __shared__ float sWq[];              // [128][129] + 128
    const float ISD = 0.08838834764831845f;
    const int tid = threadIdx.x;
    const int a = blockIdx.x;

    if (a < 128) {
        for (int idx = tid; idx < D_ * D_; idx += 128) {
            int r = idx >> 7, c = idx & 127;
            sWq[r * 129 + c] = Wq[idx];
        }
        __syncthreads();
        float accA = 0.f, accC = 0.f;
        #pragma unroll 16
        for (int d = 0; d < D_; d++) {
            accA += __ldg(&Wk[a * D_ + d]) * sWq[tid * 129 + d];
            accC += __ldg(&Wv[a * D_ + d]) * __ldg(&Wo[d * D_ + tid]);
        }
        g_A[a * D_ + tid] = accA * ISD;
        g_C[a * D_ + tid] = accC;
    } else if (a == 128) {
        for (int idx = tid; idx < D_ * D_; idx += 128) {
            int r = idx >> 7, c = idx & 127;
            sWq[r * 129 + c] = Wk[idx];
        }
        float* sred = sWq + 128 * 129;
        sred[tid] = bk[tid] * bq[tid];
        __syncthreads();
        float su = 0.f;
        #pragma unroll 16
        for (int d = 0; d < D_; d++) su += sWq[tid * 129 + d] * __ldg(&bq[d]);
        g_u[tid] = su * ISD;
        if (tid == 0) {
            float c = 0.f;
            #pragma unroll 16
            for (int d = 0; d < D_; d++) c += sred[d];
            g_c0 = c * ISD;
        }
    } else if (a == 129) {
        for (int idx = tid; idx < D_ * D_; idx += 128) {
            int r = idx >> 7, c = idx & 127;
            sWq[r * 129 + c] = Wq[idx];
        }
        __syncthreads();
        float sw = 0.f;
        #pragma unroll 16
        for (int d = 0; d < D_; d++) sw += sWq[tid * 129 + d] * __ldg(&bk[d]);
        g_w[tid] = sw * ISD;
    } else {
        float se = 0.f;
        #pragma unroll 16
        for (int d = 0; d < D_; d++) se += __ldg(&bv[d]) * __ldg(&Wo[d * D_ + tid]);
        g_e[tid] = se;
    }
}

// =======================================================================
// k_prew: split W^T images (rows = out col n, cols = k)
// =======================================================================
__global__ void __launch_bounds__(256) k_prew()
{
    const int tid = threadIdx.x;
    for (int w = tid; w < 8192; w += 256) {
        int n = w >> 6, d0 = (w & 63) * 2;
        u32 hw, lw;
        split2(g_A[d0 * 128 + n], g_A[(d0 + 1) * 128 + n], hw, lw);
        g_WAhi[w] = hw; g_WAlo[w] = lw;
        split2(g_C[d0 * 128 + n], g_C[(d0 + 1) * 128 + n], hw, lw);
        g_WChi[w] = hw; g_WClo[w] = lw;
    }
}

// =======================================================================
// k_split: S fp32 -> split bf16 gmem + rj/ck dot products. grid 1024 x 256
// =======================================================================
__global__ void __launch_bounds__(256) k_split(const float* __restrict__ S)
{
    const int lane = threadIdx.x & 31;
    const int wg = blockIdx.x * 8 + (threadIdx.x >> 5);
    const float4 uv = *reinterpret_cast<const float4*>(&g_u[lane * 4]);
    const float4 wv = *reinterpret_cast<const float4*>(&g_w[lane * 4]);
    const float c0 = g_c0;

    for (int i = 0; i < 16; i++) {
        const long row = (long)wg * 16 + i;
        float4 s = __ldg(reinterpret_cast<const float4*>(&S[row * D_ + lane * 4]));
        float du = s.x * uv.x + s.y * uv.y + s.z * uv.z + s.w * uv.w;
        float dw = s.x * wv.x + s.y * wv.y + s.z * wv.z + s.w * wv.w;
        #pragma unroll
        for (int off = 16; off > 0; off >>= 1) {
            du += __shfl_xor_sync(0xFFFFFFFFu, du, off);
            dw += __shfl_xor_sync(0xFFFFFFFFu, dw, off);
        }
        if (lane == 0) { g_rj[row] = du + c0; g_ck[row] = dw; }
        u32 h0, l0, h1, l1;
        split2(s.x, s.y, h0, l0);
        split2(s.z, s.w, h1, l1);
        g_Shi[row * 64 + lane * 2]     = h0;
        g_Shi[row * 64 + lane * 2 + 1] = h1;
        g_Slo[row * 64 + lane * 2]     = l0;
        g_Slo[row * 64 + lane * 2 + 1] = l1;
    }
}

// =======================================================================
// k_proj: T = S@A (which=0) or U = S@C (which=1) via mma.sync bf16 split.
// grid 2048, block 256 (8 warps, 4m x 2n, warp tile 32x64), smem 6 images.
// =======================================================================
#define PJ_SMEM (6 * IMG_W * 4)

__global__ void __launch_bounds__(256) k_proj()
{
    extern __shared__ u32 smp[];
    u32* SHI = smp;
    u32* SLO = SHI + IMG_W;
    u32* WHI = SLO + IMG_W;
    u32* WLO = WHI + IMG_W;
    u32* OH  = WLO + IMG_W;
    u32* OL  = OH + IMG_W;

    const int tid = threadIdx.x;
    const int warp = tid >> 5, lane = tid & 31;
    const int g = lane >> 2, t = lane & 3;
    const int m0 = (warp & 3) * 32, n0 = (warp >> 2) * 64;

    const int idx = blockIdx.x;
    const int which = idx >> 10;
    const long rb = (long)(idx & 1023) * 128;

    for (int w = tid; w < 8192; w += 256) {
        int r = w >> 6, c = w & 63;
        SHI[r * KPW + c] = g_Shi[rb * 64 + w];
        SLO[r * KPW + c] = g_Slo[rb * 64 + w];
    }
    const u32* gwh = which ? g_WChi : g_WAhi;
    const u32* gwl = which ? g_WClo : g_WAlo;
    for (int w = tid; w < 8192; w += 256) {
        int r = w >> 6, c = w & 63;
        WHI[r * KPW + c] = gwh[w];
        WLO[r * KPW + c] = gwl[w];
    }
    __syncthreads();

    float acc[2][8][4];
    #pragma unroll
    for (int mf = 0; mf < 2; mf++)
        #pragma unroll
        for (int nf = 0; nf < 8; nf++)
            #pragma unroll
            for (int q = 0; q < 4; q++) acc[mf][nf][q] = 0.f;

    gemm3p(acc, SHI, SLO, WHI, WLO, m0, n0, g, t);

    if (which == 0) {
        // T: split + store [row][k] directly
        #pragma unroll
        for (int mf = 0; mf < 2; mf++) {
            #pragma unroll
            for (int half = 0; half < 2; half++) {
                const long r = rb + m0 + mf * 16 + g + half * 8;
                #pragma unroll
                for (int nf = 0; nf < 8; nf++) {
                    const int cw = (n0 + nf * 8) / 2 + t;   // word col
                    u32 hw, lw;
                    split2(acc[mf][nf][half * 2], acc[mf][nf][half * 2 + 1], hw, lw);
                    g_Thi[r * 64 + cw] = hw;
                    g_Tlo[r * 64 + cw] = lw;
                }
            }
        }
    } else {
        // U: transpose via smem -> U^T [d][kk]
        __nv_bfloat16* oh = (__nv_bfloat16*)OH;
        __nv_bfloat16* ol = (__nv_bfloat16*)OL;
        #pragma unroll
        for (int mf = 0; mf < 2; mf++) {
            #pragma unroll
            for (int half = 0; half < 2; half++) {
                const int kkL = m0 + mf * 16 + g + half * 8;
                #pragma unroll
                for (int nf = 0; nf < 8; nf++) {
                    const int d0 = n0 + nf * 8 + 2 * t;
                    __nv_bfloat16 h, l;
                    split1(acc[mf][nf][half * 2], h, l);
                    oh[d0 * 136 + kkL] = h; ol[d0 * 136 + kkL] = l;
                    split1(acc[mf][nf][half * 2 + 1], h, l);
                    oh[(d0 + 1) * 136 + kkL] = h; ol[(d0 + 1) * 136 + kkL] = l;
                }
            }
        }
        __syncthreads();
        const int bi = (int)(rb >> 8);
        const int kh = (int)((rb >> 7) & 1);
        for (int w = tid; w < 8192; w += 256) {
            int d = w >> 6, c = w & 63;
            const long go = ((long)bi * 128 + d) * 128 + kh * 64 + c;
            g_Uthi[go] = OH[d * KPW + c];
            g_Utlo[go] = OL[d * KPW + c];
        }
    }
}

// =======================================================================
// k_attn: per (bi, jh): scores -> relu/bias/rowsum -> P -> out += P@U^T;
// fused residual + LayerNorm.  grid 1024, block 256, smem 6 images + ~3KB.
// =======================================================================
#define KA_SMEM (6 * IMG_W * 4 + (128 + 256 + 128 + 128 + 128) * 4)

__global__ void __launch_bounds__(256) k_attn(
    const float* __restrict__ S, const float* __restrict__ bo,
    const float* __restrict__ ln_g, const float* __restrict__ ln_b,
    float* __restrict__ out)
{
    extern __shared__ u32 sma[];
    u32* THI = sma;
    u32* TLO = THI + IMG_W;
    u32* PHI = TLO + IMG_W;    // S tile, later P
    u32* PLO = PHI + IMG_W;
    u32* UHI = PLO + IMG_W;
    u32* ULO = UHI + IMG_W;
    float* srj   = (float*)(ULO + IMG_W);  // 128
    float* sck   = srj + 128;              // 256
    float* sRow  = sck + 256;              // 128
    float* sMu   = sRow + 128;             // 128
    float* sRstd = sMu + 128;              // 128
    float* sx    = (float*)THI;            // epilogue overlay [128][133]

    const int tid = threadIdx.x;
    const int warp = tid >> 5, lane = tid & 31;
    const int g = lane >> 2, t = lane & 3;
    const int m0 = (warp & 3) * 32, n0 = (warp >> 2) * 64;

    const int bij = blockIdx.x;
    const int bi = bij >> 1, jh = bij & 1;
    const long rT = (long)bij * 128;       // global row of this CTA's first j

    for (int w = tid; w < 8192; w += 256) {
        int r = w >> 6, c = w & 63;
        THI[r * KPW + c] = g_Thi[rT * 64 + w];
        TLO[r * KPW + c] = g_Tlo[rT * 64 + w];
    }
    if (tid < 128) { srj[tid] = g_rj[rT + tid]; sRow[tid] = 0.f; }
    sck[tid] = g_ck[(long)bi * 256 + tid];   // 256 threads = 256 entries

    float acc2[2][8][4];
    #pragma unroll
    for (int mf = 0; mf < 2; mf++)
        #pragma unroll
        for (int nf = 0; nf < 8; nf++)
            #pragma unroll
            for (int q = 0; q < 4; q++) acc2[mf][nf][q] = 0.f;

    for (int t2 = 0; t2 < 2; t2++) {
        __syncthreads();   // prev GEMM2 done (t2>0); sRow/sck init (t2==0)
        const long sr = ((long)bi * 256 + t2 * 128) * 64;
        for (int w = tid; w < 8192; w += 256) {
            int r = w >> 6, c = w & 63;
            PHI[r * KPW + c] = g_Shi[sr + w];
            PLO[r * KPW + c] = g_Slo[sr + w];
        }
        for (int w = tid; w < 8192; w += 256) {
            int d = w >> 6, c = w & 63;
            const long go = ((long)bi * 128 + d) * 128 + t2 * 64 + c;
            UHI[d * KPW + c] = g_Uthi[go];
            ULO[d * KPW + c] = g_Utlo[go];
        }
        __syncthreads();

        // GEMM1: scores = T . S^T
        float acc1[2][8][4];
        #pragma unroll
        for (int mf = 0; mf < 2; mf++)
            #pragma unroll
            for (int nf = 0; nf < 8; nf++)
                #pragma unroll
                for (int q = 0; q < 4; q++) acc1[mf][nf][q] = 0.f;
        gemm3p(acc1, THI, TLO, PHI, PLO, m0, n0, g, t);
        __syncthreads();   // all warps done reading S tile

        // P = relu(scores + rj + ck), split into PHI/PLO, rowsum
        #pragma unroll
        for (int mf = 0; mf < 2; mf++) {
            #pragma unroll
            for (int half = 0; half < 2; half++) {
                const int j = m0 + mf * 16 + g + half * 8;
                const float rj = srj[j];
                float rsum = 0.f;
                #pragma unroll
                for (int nf = 0; nf < 8; nf++) {
                    const int kk = n0 + nf * 8 + 2 * t;
                    float p0 = fmaxf(acc1[mf][nf][half * 2]     + rj + sck[t2 * 128 + kk],     0.f);
                    float p1 = fmaxf(acc1[mf][nf][half * 2 + 1] + rj + sck[t2 * 128 + kk + 1], 0.f);
                    rsum += p0 + p1;
                    u32 hw, lw;
                    split2(p0, p1, hw, lw);
                    PHI[j * KPW + kk / 2] = hw;
                    PLO[j * KPW + kk / 2] = lw;
                }
                rsum += __shfl_xor_sync(0xFFFFFFFFu, rsum, 1);
                rsum += __shfl_xor_sync(0xFFFFFFFFu, rsum, 2);
                if (t == 0) atomicAdd(&sRow[j], rsum);
            }
        }
        __syncthreads();

        // GEMM2: out += P . U^T
        gemm3p(acc2, PHI, PLO, UHI, ULO, m0, n0, g, t);
    }
    __syncthreads();   // sRow final; T images free

    // epilogue: x = out + rowsum*e + bo + S  -> sx
    const float* Sb = S + ((long)bi * 256 + jh * 128) * D_;
    #pragma unroll
    for (int mf = 0; mf < 2; mf++) {
        #pragma unroll
        for (int half = 0; half < 2; half++) {
            const int j = m0 + mf * 16 + g + half * 8;
            const float rs = sRow[j];
            #pragma unroll
            for (int nf = 0; nf < 8; nf++) {
                const int d = n0 + nf * 8 + 2 * t;
                float2 sv = __ldg(reinterpret_cast<const float2*>(&Sb[(long)j * D_ + d]));
                float x0 = acc2[mf][nf][half * 2]     + rs * __ldg(&g_e[d])     + __ldg(&bo[d])     + sv.x;
                float x1 = acc2[mf][nf][half * 2 + 1] + rs * __ldg(&g_e[d + 1]) + __ldg(&bo[d + 1]) + sv.y;
                sx[j * 133 + d]     = x0;
                sx[j * 133 + d + 1] = x1;
            }
        }
    }
    __syncthreads();

    if (tid < 128) {
        float s = 0.f, s2 = 0.f;
        #pragma unroll 8
        for (int d = 0; d < D_; d++) {
            float v = sx[tid * 133 + d];
            s += v; s2 += v * v;
        }
        float mu = s * (1.f / 128.f);
        float var = s2 * (1.f / 128.f) - mu * mu;
        sMu[tid] = mu;
        sRstd[tid] = rsqrtf(var + 1e-5f);
    }
    __syncthreads();

    float* op = out + ((long)bi * 256 + jh * 128) * D_;
    for (int idx = tid; idx < 128 * D_; idx += 256) {
        int j = idx >> 7, d = idx & 127;
        op[idx] = (sx[j * 133 + d] - sMu[j]) * sRstd[j] * __ldg(&ln_g[d]) + __ldg(&ln_b[d]);
    }
}

// =======================================================================
// launch
// =======================================================================
extern "C" void kernel_launch(void* const* d_in, const int* in_sizes, int n_in,
                              void* d_out, int out_size)
{
    (void)in_sizes; (void)n_in; (void)out_size;
    const float* S    = (const float*)d_in[1];
    const float* Wq   = (const float*)d_in[2];
    const float* bq   = (const float*)d_in[3];
    const float* Wk   = (const float*)d_in[4];
    const float* bk   = (const float*)d_in[5];
    const float* Wv   = (const float*)d_in[6];
    const float* bv   = (const float*)d_in[7];
    const float* Wo   = (const float*)d_in[8];
    const float* bo   = (const float*)d_in[9];
    const float* ln_g = (const float*)d_in[10];
    const float* ln_b = (const float*)d_in[11];
    float* out = (float*)d_out;

    const size_t sm0 = (size_t)(128 * 129 + 128) * sizeof(float);
    cudaFuncSetAttribute(k_pre,  cudaFuncAttributeMaxDynamicSharedMemorySize, (int)sm0);
    cudaFuncSetAttribute(k_proj, cudaFuncAttributeMaxDynamicSharedMemorySize, PJ_SMEM);
    cudaFuncSetAttribute(k_attn, cudaFuncAttributeMaxDynamicSharedMemorySize, KA_SMEM);

    k_pre  <<<131, 128, sm0>>>(Wq, bq, Wk, bk, Wv, bv, Wo);
    k_prew <<<1, 256>>>();
    k_split<<<1024, 256>>>(S);
    k_proj <<<2048, 256, PJ_SMEM>>>();
    k_attn <<<1024, 256, KA_SMEM>>>(S, bo, ln_g, ln_b, out);
}

// round 8
// speedup vs baseline: 2.1424x; 1.2725x over previous
#include <cuda_runtime.h>
#include <cuda_bf16.h>
#include <stdint.h>

#define DI __device__ __forceinline__
typedef uint32_t u32;

#define N_ 256
#define D_ 128
#define NBI 512
#define ROWS_TOTAL (NBI * N_)       // 131072

#define KPW 68                      // u32 words per row in smem operand images
#define IMG_W (128 * KPW)           // 8704 words = 34816 B per image

// ---------------- global scratch (static: allowed) ----------------
__device__ float g_A[D_ * D_];
__device__ float g_C[D_ * D_];
__device__ __align__(16) float g_u[D_];
__device__ __align__(16) float g_w[D_];
__device__ __align__(16) float g_e[D_];
__device__ float g_c0;
__device__ float g_rj[ROWS_TOTAL], g_ck[ROWS_TOTAL];

__device__ u32 g_Shi[ROWS_TOTAL * 64];   // S split bf16 [row][64 words]
__device__ u32 g_Slo[ROWS_TOTAL * 64];
__device__ u32 g_Thi[ROWS_TOTAL * 64];   // T split bf16
__device__ u32 g_Tlo[ROWS_TOTAL * 64];
__device__ u32 g_Uthi[(size_t)NBI * 128 * 128];  // U^T split [bi][d][128 words]
__device__ u32 g_Utlo[(size_t)NBI * 128 * 128];
__device__ u32 g_WAhi[8192], g_WAlo[8192];       // A^T image [n][64 words]
__device__ u32 g_WChi[8192], g_WClo[8192];       // C^T image

// ---------------- helpers ----------------
DI u32 sa(const void* p) {
    u32 a; asm("{ .reg .u64 t; cvta.to.shared.u64 t, %1; cvt.u32.u64 %0, t; }" : "=r"(a) : "l"(p));
    return a;
}
DI void cpa16(u32 dst, const void* src) {
    asm volatile("cp.async.cg.shared.global [%0], [%1], 16;" :: "r"(dst), "l"(src) : "memory");
}
DI void cpa_wait() { asm volatile("cp.async.wait_all;" ::: "memory"); }

DI void split2(float v0, float v1, u32& hw, u32& lw) {
    __nv_bfloat16 h0 = __float2bfloat16(v0), h1 = __float2bfloat16(v1);
    float r0 = v0 - __bfloat162float(h0), r1 = v1 - __bfloat162float(h1);
    __nv_bfloat16 l0 = __float2bfloat16(r0), l1 = __float2bfloat16(r1);
    hw = (u32)__bfloat16_as_ushort(h0) | ((u32)__bfloat16_as_ushort(h1) << 16);
    lw = (u32)__bfloat16_as_ushort(l0) | ((u32)__bfloat16_as_ushort(l1) << 16);
}
DI void split1(float v, __nv_bfloat16& h, __nv_bfloat16& l) {
    h = __float2bfloat16(v);
    l = __float2bfloat16(v - __bfloat162float(h));
}

DI void ldm4(u32* r, u32 addr) {
    asm volatile("ldmatrix.sync.aligned.m8n8.x4.shared.b16 {%0,%1,%2,%3}, [%4];"
        : "=r"(r[0]), "=r"(r[1]), "=r"(r[2]), "=r"(r[3]) : "r"(addr));
}
DI void mma_bf16(float* c, u32 a0, u32 a1, u32 a2, u32 a3, u32 b0, u32 b1) {
    asm volatile(
        "mma.sync.aligned.m16n8k16.row.col.f32.bf16.bf16.f32 "
        "{%0,%1,%2,%3}, {%4,%5,%6,%7}, {%8,%9}, {%0,%1,%2,%3};"
        : "+f"(c[0]), "+f"(c[1]), "+f"(c[2]), "+f"(c[3])
        : "r"(a0), "r"(a1), "r"(a2), "r"(a3), "r"(b0), "r"(b1));
}

// K=128 product into warp tile 32(m) x 32(n) via ldmatrix; images [row][KPW words]
DI void mma_k128(float acc[2][4][4], u32 Ab, u32 Bb, int m0, int n0, int lane) {
    const u32 aoff = Ab + (u32)(((m0 + (lane & 15)) * KPW + ((lane >> 4) << 2)) * 4);
    const u32 boff = Bb + (u32)(((n0 + ((lane >> 4) << 3) + (lane & 7)) * KPW
                                 + (((lane >> 3) & 1) << 2)) * 4);
    #pragma unroll
    for (int ks = 0; ks < 8; ks++) {
        u32 a[2][4], b[2][4];
        #pragma unroll
        for (int mf = 0; mf < 2; mf++) ldm4(a[mf], aoff + (u32)(mf * 16 * KPW * 4) + ks * 32);
        #pragma unroll
        for (int ng = 0; ng < 2; ng++) ldm4(b[ng], boff + (u32)(ng * 16 * KPW * 4) + ks * 32);
        #pragma unroll
        for (int mf = 0; mf < 2; mf++)
            #pragma unroll
            for (int ng = 0; ng < 2; ng++) {
                mma_bf16(acc[mf][ng * 2],     a[mf][0], a[mf][1], a[mf][2], a[mf][3], b[ng][0], b[ng][1]);
                mma_bf16(acc[mf][ng * 2 + 1], a[mf][0], a[mf][1], a[mf][2], a[mf][3], b[ng][2], b[ng][3]);
            }
    }
}
DI void gemm3p(float acc[2][4][4], u32 AH, u32 AL, u32 BH, u32 BL, int m0, int n0, int lane) {
    mma_k128(acc, AH, BH, m0, n0, lane);
    mma_k128(acc, AH, BL, m0, n0, lane);
    mma_k128(acc, AL, BH, m0, n0, lane);
}

// =======================================================================
// k_pre: fold weights (fp32, proven)
// =======================================================================
__global__ void __launch_bounds__(128) k_pre(
    const float* __restrict__ Wq, const float* __restrict__ bq,
    const float* __restrict__ Wk, const float* __restrict__ bk,
    const float* __restrict__ Wv, const float* __restrict__ bv,
    const float* __restrict__ Wo)
{
    extern __shared__ float sWq[];
    const float ISD = 0.08838834764831845f;
    const int tid = threadIdx.x;
    const int a = blockIdx.x;

    if (a < 128) {
        for (int idx = tid; idx < D_ * D_; idx += 128) {
            int r = idx >> 7, c = idx & 127;
            sWq[r * 129 + c] = Wq[idx];
        }
        __syncthreads();
        float accA = 0.f, accC = 0.f;
        #pragma unroll 16
        for (int d = 0; d < D_; d++) {
            accA += __ldg(&Wk[a * D_ + d]) * sWq[tid * 129 + d];
            accC += __ldg(&Wv[a * D_ + d]) * __ldg(&Wo[d * D_ + tid]);
        }
        g_A[a * D_ + tid] = accA * ISD;
        g_C[a * D_ + tid] = accC;
    } else if (a == 128) {
        for (int idx = tid; idx < D_ * D_; idx += 128) {
            int r = idx >> 7, c = idx & 127;
            sWq[r * 129 + c] = Wk[idx];
        }
        float* sred = sWq + 128 * 129;
        sred[tid] = bk[tid] * bq[tid];
        __syncthreads();
        float su = 0.f;
        #pragma unroll 16
        for (int d = 0; d < D_; d++) su += sWq[tid * 129 + d] * __ldg(&bq[d]);
        g_u[tid] = su * ISD;
        if (tid == 0) {
            float c = 0.f;
            #pragma unroll 16
            for (int d = 0; d < D_; d++) c += sred[d];
            g_c0 = c * ISD;
        }
    } else if (a == 129) {
        for (int idx = tid; idx < D_ * D_; idx += 128) {
            int r = idx >> 7, c = idx & 127;
            sWq[r * 129 + c] = Wq[idx];
        }
        __syncthreads();
        float sw = 0.f;
        #pragma unroll 16
        for (int d = 0; d < D_; d++) sw += sWq[tid * 129 + d] * __ldg(&bk[d]);
        g_w[tid] = sw * ISD;
    } else {
        float se = 0.f;
        #pragma unroll 16
        for (int d = 0; d < D_; d++) se += __ldg(&bv[d]) * __ldg(&Wo[d * D_ + tid]);
        g_e[tid] = se;
    }
}

// =======================================================================
// k_prew: split W^T images (rows = out col n, cols = k)
// =======================================================================
__global__ void __launch_bounds__(256) k_prew()
{
    const int tid = threadIdx.x;
    for (int w = tid; w < 8192; w += 256) {
        int n = w >> 6, d0 = (w & 63) * 2;
        u32 hw, lw;
        split2(g_A[d0 * 128 + n], g_A[(d0 + 1) * 128 + n], hw, lw);
        g_WAhi[w] = hw; g_WAlo[w] = lw;
        split2(g_C[d0 * 128 + n], g_C[(d0 + 1) * 128 + n], hw, lw);
        g_WChi[w] = hw; g_WClo[w] = lw;
    }
}

// =======================================================================
// k_split: S fp32 -> split bf16 gmem + rj/ck dots. grid 1024 x 256
// =======================================================================
__global__ void __launch_bounds__(256) k_split(const float* __restrict__ S)
{
    const int lane = threadIdx.x & 31;
    const int wg = blockIdx.x * 8 + (threadIdx.x >> 5);
    const float4 uv = *reinterpret_cast<const float4*>(&g_u[lane * 4]);
    const float4 wv = *reinterpret_cast<const float4*>(&g_w[lane * 4]);
    const float c0 = g_c0;

    for (int i = 0; i < 16; i++) {
        const long row = (long)wg * 16 + i;
        float4 s = __ldg(reinterpret_cast<const float4*>(&S[row * D_ + lane * 4]));
        float du = s.x * uv.x + s.y * uv.y + s.z * uv.z + s.w * uv.w;
        float dw = s.x * wv.x + s.y * wv.y + s.z * wv.z + s.w * wv.w;
        #pragma unroll
        for (int off = 16; off > 0; off >>= 1) {
            du += __shfl_xor_sync(0xFFFFFFFFu, du, off);
            dw += __shfl_xor_sync(0xFFFFFFFFu, dw, off);
        }
        if (lane == 0) { g_rj[row] = du + c0; g_ck[row] = dw; }
        u32 h0, l0, h1, l1;
        split2(s.x, s.y, h0, l0);
        split2(s.z, s.w, h1, l1);
        g_Shi[row * 64 + lane * 2]     = h0;
        g_Shi[row * 64 + lane * 2 + 1] = h1;
        g_Slo[row * 64 + lane * 2]     = l0;
        g_Slo[row * 64 + lane * 2 + 1] = l1;
    }
}

// =======================================================================
// k_proj: T = S@A and U = S@C in one CTA.  grid 1024, block 512 (16 warps,
// warp tile 32x32), smem 6 images (S hi/lo, WA hi/lo, WC hi/lo).
// =======================================================================
#define PJ_SMEM (6 * IMG_W * 4)

__global__ void __launch_bounds__(512) k_proj()
{
    extern __shared__ u32 smp[];
    u32* SHI = smp;
    u32* SLO = SHI + IMG_W;
    u32* WAH = SLO + IMG_W;
    u32* WAL = WAH + IMG_W;
    u32* WCH = WAL + IMG_W;
    u32* WCL = WCH + IMG_W;

    const int tid = threadIdx.x;
    const int warp = tid >> 5, lane = tid & 31;
    const int g = lane >> 2, t = lane & 3;
    const int m0 = (warp & 3) * 32, n0 = (warp >> 2) * 32;
    const long rb = (long)blockIdx.x * 128;

    const u32 aSHI = sa(SHI), aSLO = sa(SLO), aWAH = sa(WAH), aWAL = sa(WAL),
              aWCH = sa(WCH), aWCL = sa(WCL);

    for (int i = tid; i < 2048; i += 512) {
        int r = i >> 4, c4 = (i & 15) << 2;
        u32 doff = (u32)((r * KPW + c4) * 4);
        cpa16(aSHI + doff, g_Shi + rb * 64 + r * 64 + c4);
        cpa16(aSLO + doff, g_Slo + rb * 64 + r * 64 + c4);
        cpa16(aWAH + doff, g_WAhi + r * 64 + c4);
        cpa16(aWAL + doff, g_WAlo + r * 64 + c4);
        cpa16(aWCH + doff, g_WChi + r * 64 + c4);
        cpa16(aWCL + doff, g_WClo + r * 64 + c4);
    }
    cpa_wait();
    __syncthreads();

    float acc[2][4][4];
    #pragma unroll
    for (int mf = 0; mf < 2; mf++)
        #pragma unroll
        for (int nf = 0; nf < 4; nf++)
            #pragma unroll
            for (int q = 0; q < 4; q++) acc[mf][nf][q] = 0.f;

    // ---- T = S @ A ----
    gemm3p(acc, aSHI, aSLO, aWAH, aWAL, m0, n0, lane);
    #pragma unroll
    for (int mf = 0; mf < 2; mf++)
        #pragma unroll
        for (int half = 0; half < 2; half++) {
            const long r = rb + m0 + mf * 16 + g + half * 8;
            #pragma unroll
            for (int nf = 0; nf < 4; nf++) {
                const int cw = (n0 + nf * 8) / 2 + t;
                u32 hw, lw;
                split2(acc[mf][nf][half * 2], acc[mf][nf][half * 2 + 1], hw, lw);
                g_Thi[r * 64 + cw] = hw;
                g_Tlo[r * 64 + cw] = lw;
            }
        }
    __syncthreads();   // all warps done reading WA images

    // ---- U = S @ C ----
    #pragma unroll
    for (int mf = 0; mf < 2; mf++)
        #pragma unroll
        for (int nf = 0; nf < 4; nf++)
            #pragma unroll
            for (int q = 0; q < 4; q++) acc[mf][nf][q] = 0.f;
    gemm3p(acc, aSHI, aSLO, aWCH, aWCL, m0, n0, lane);

    // transpose U into WA area (free now): OH/OL [d][128 kk] bf16, stride 136
    __nv_bfloat16* oh = (__nv_bfloat16*)WAH;
    __nv_bfloat16* ol = (__nv_bfloat16*)WAL;
    #pragma unroll
    for (int mf = 0; mf < 2; mf++)
        #pragma unroll
        for (int half = 0; half < 2; half++) {
            const int kkL = m0 + mf * 16 + g + half * 8;
            #pragma unroll
            for (int nf = 0; nf < 4; nf++) {
                const int d0 = n0 + nf * 8 + 2 * t;
                __nv_bfloat16 h, l;
                split1(acc[mf][nf][half * 2], h, l);
                oh[d0 * 136 + kkL] = h; ol[d0 * 136 + kkL] = l;
                split1(acc[mf][nf][half * 2 + 1], h, l);
                oh[(d0 + 1) * 136 + kkL] = h; ol[(d0 + 1) * 136 + kkL] = l;
            }
        }
    __syncthreads();

    const int bi = blockIdx.x >> 1;
    const int kh = blockIdx.x & 1;
    for (int w = tid; w < 8192; w += 512) {
        int d = w >> 6, c = w & 63;
        const long go = ((long)bi * 128 + d) * 128 + kh * 64 + c;
        g_Uthi[go] = WAH[d * KPW + c];
        g_Utlo[go] = WAL[d * KPW + c];
    }
}

// =======================================================================
// k_attn: per (bi, jh): GEMM1 -> relu/bias/rowsum -> P -> GEMM2; fused
// residual + LayerNorm.  grid 1024, block 512, smem 6 images + ~3KB.
// =======================================================================
#define KA_SMEM (6 * IMG_W * 4 + (128 + 256 + 128 + 128 + 128) * 4)

__global__ void __launch_bounds__(512) k_attn(
    const float* __restrict__ S, const float* __restrict__ bo,
    const float* __restrict__ ln_g, const float* __restrict__ ln_b,
    float* __restrict__ out)
{
    extern __shared__ u32 sma[];
    u32* THI = sma;
    u32* TLO = THI + IMG_W;
    u32* PHI = TLO + IMG_W;    // S tile, later P
    u32* PLO = PHI + IMG_W;
    u32* UHI = PLO + IMG_W;
    u32* ULO = UHI + IMG_W;
    float* srj   = (float*)(ULO + IMG_W);  // 128
    float* sck   = srj + 128;              // 256
    float* sRow  = sck + 256;              // 128
    float* sMu   = sRow + 128;             // 128
    float* sRstd = sMu + 128;              // 128
    float* sx    = (float*)THI;            // epilogue overlay [128][133]

    const int tid = threadIdx.x;
    const int warp = tid >> 5, lane = tid & 31;
    const int g = lane >> 2, t = lane & 3;
    const int m0 = (warp & 3) * 32, n0 = (warp >> 2) * 32;

    const int bij = blockIdx.x;
    const int bi = bij >> 1, jh = bij & 1;
    const long rT = (long)bij * 128;

    const u32 aTHI = sa(THI), aTLO = sa(TLO), aPHI = sa(PHI), aPLO = sa(PLO),
              aUHI = sa(UHI), aULO = sa(ULO);

    for (int i = tid; i < 2048; i += 512) {
        int r = i >> 4, c4 = (i & 15) << 2;
        u32 doff = (u32)((r * KPW + c4) * 4);
        cpa16(aTHI + doff, g_Thi + rT * 64 + r * 64 + c4);
        cpa16(aTLO + doff, g_Tlo + rT * 64 + r * 64 + c4);
    }
    if (tid < 128) { srj[tid] = g_rj[rT + tid]; sRow[tid] = 0.f; }
    if (tid < 256) sck[tid] = g_ck[(long)bi * 256 + tid];

    float acc2[2][4][4];
    #pragma unroll
    for (int mf = 0; mf < 2; mf++)
        #pragma unroll
        for (int nf = 0; nf < 4; nf++)
            #pragma unroll
            for (int q = 0; q < 4; q++) acc2[mf][nf][q] = 0.f;

    for (int t2 = 0; t2 < 2; t2++) {
        __syncthreads();   // prev GEMM2 done; (t2==0) srj/sck/sRow visible
        const long sr = ((long)bi * 256 + t2 * 128) * 64;
        for (int i = tid; i < 2048; i += 512) {
            int r = i >> 4, c4 = (i & 15) << 2;
            u32 doff = (u32)((r * KPW + c4) * 4);
            cpa16(aPHI + doff, g_Shi + sr + r * 64 + c4);
            cpa16(aPLO + doff, g_Slo + sr + r * 64 + c4);
            const long go = ((long)bi * 128 + r) * 128 + t2 * 64 + c4;
            cpa16(aUHI + doff, g_Uthi + go);
            cpa16(aULO + doff, g_Utlo + go);
        }
        cpa_wait();
        __syncthreads();

        // GEMM1: scores = T . S^T
        float acc1[2][4][4];
        #pragma unroll
        for (int mf = 0; mf < 2; mf++)
            #pragma unroll
            for (int nf = 0; nf < 4; nf++)
                #pragma unroll
                for (int q = 0; q < 4; q++) acc1[mf][nf][q] = 0.f;
        gemm3p(acc1, aTHI, aTLO, aPHI, aPLO, m0, n0, lane);
        __syncthreads();   // all warps done reading S tile

        // P = relu(scores + rj + ck) -> PHI/PLO, rowsum
        #pragma unroll
        for (int mf = 0; mf < 2; mf++)
            #pragma unroll
            for (int half = 0; half < 2; half++) {
                const int j = m0 + mf * 16 + g + half * 8;
                const float rj = srj[j];
                float rsum = 0.f;
                #pragma unroll
                for (int nf = 0; nf < 4; nf++) {
                    const int kk = n0 + nf * 8 + 2 * t;
                    float p0 = fmaxf(acc1[mf][nf][half * 2]     + rj + sck[t2 * 128 + kk],     0.f);
                    float p1 = fmaxf(acc1[mf][nf][half * 2 + 1] + rj + sck[t2 * 128 + kk + 1], 0.f);
                    rsum += p0 + p1;
                    u32 hw, lw;
                    split2(p0, p1, hw, lw);
                    const int cw = (n0 + nf * 8) / 2 + t;
                    PHI[j * KPW + cw] = hw;
                    PLO[j * KPW + cw] = lw;
                }
                rsum += __shfl_xor_sync(0xFFFFFFFFu, rsum, 1);
                rsum += __shfl_xor_sync(0xFFFFFFFFu, rsum, 2);
                if (t == 0) atomicAdd(&sRow[j], rsum);
            }
        __syncthreads();

        // GEMM2: out += P . U^T
        gemm3p(acc2, aPHI, aPLO, aUHI, aULO, m0, n0, lane);
    }
    __syncthreads();   // sRow final; THI/TLO free

    // epilogue: x = out + rowsum*e + bo + S  -> sx
    const float* Sb = S + ((long)bi * 256 + jh * 128) * D_;
    #pragma unroll
    for (int mf = 0; mf < 2; mf++)
        #pragma unroll
        for (int half = 0; half < 2; half++) {
            const int j = m0 + mf * 16 + g + half * 8;
            const float rs = sRow[j];
            #pragma unroll
            for (int nf = 0; nf < 4; nf++) {
                const int d = n0 + nf * 8 + 2 * t;
                float2 sv = __ldg(reinterpret_cast<const float2*>(&Sb[(long)j * D_ + d]));
                float x0 = acc2[mf][nf][half * 2]     + rs * __ldg(&g_e[d])     + __ldg(&bo[d])     + sv.x;
                float x1 = acc2[mf][nf][half * 2 + 1] + rs * __ldg(&g_e[d + 1]) + __ldg(&bo[d + 1]) + sv.y;
                sx[j * 133 + d]     = x0;
                sx[j * 133 + d + 1] = x1;
            }
        }
    __syncthreads();

    if (tid < 128) {
        float s = 0.f, s2 = 0.f;
        #pragma unroll 8
        for (int d = 0; d < D_; d++) {
            float v = sx[tid * 133 + d];
            s += v; s2 += v * v;
        }
        float mu = s * (1.f / 128.f);
        float var = s2 * (1.f / 128.f) - mu * mu;
        sMu[tid] = mu;
        sRstd[tid] = rsqrtf(var + 1e-5f);
    }
    __syncthreads();

    float* op = out + ((long)bi * 256 + jh * 128) * D_;
    for (int idx = tid; idx < 128 * D_; idx += 512) {
        int j = idx >> 7, d = idx & 127;
        op[idx] = (sx[j * 133 + d] - sMu[j]) * sRstd[j] * __ldg(&ln_g[d]) + __ldg(&ln_b[d]);
    }
}

// =======================================================================
// launch
// =======================================================================
extern "C" void kernel_launch(void* const* d_in, const int* in_sizes, int n_in,
                              void* d_out, int out_size)
{
    (void)in_sizes; (void)n_in; (void)out_size;
    const float* S    = (const float*)d_in[1];
    const float* Wq   = (const float*)d_in[2];
    const float* bq   = (const float*)d_in[3];
    const float* Wk   = (const float*)d_in[4];
    const float* bk   = (const float*)d_in[5];
    const float* Wv   = (const float*)d_in[6];
    const float* bv   = (const float*)d_in[7];
    const float* Wo   = (const float*)d_in[8];
    const float* bo   = (const float*)d_in[9];
    const float* ln_g = (const float*)d_in[10];
    const float* ln_b = (const float*)d_in[11];
    float* out = (float*)d_out;

    const size_t sm0 = (size_t)(128 * 129 + 128) * sizeof(float);
    cudaFuncSetAttribute(k_pre,  cudaFuncAttributeMaxDynamicSharedMemorySize, (int)sm0);
    cudaFuncSetAttribute(k_proj, cudaFuncAttributeMaxDynamicSharedMemorySize, PJ_SMEM);
    cudaFuncSetAttribute(k_attn, cudaFuncAttributeMaxDynamicSharedMemorySize, KA_SMEM);

    k_pre  <<<131, 128, sm0>>>(Wq, bq, Wk, bk, Wv, bv, Wo);
    k_prew <<<1, 256>>>();
    k_split<<<1024, 256>>>(S);
    k_proj <<<1024, 512, PJ_SMEM>>>();
    k_attn <<<1024, 512, KA_SMEM>>>(S, bo, ln_g, ln_b, out);
}